// round 14
// baseline (speedup 1.0000x reference)
#include <cuda_runtime.h>
#include <cuda_bf16.h>
#include <math.h>

// CropRoi: f (B=4, C=64, 32,32,32) f32; proposals (N,8) [b,score,cx,cy,cz,sx,sy,sz]
// out (N,C,7,7,7) f32. dims_max=32, R=7. L=c1-c0 in [2,13] => bin widths in [1,3].
//
// Warp-uniform mapping: warp-task = (proposal n, 4-ch group cg, bin i, bin j).
// Within a warp: lane = c_sub*8 + k  (c_sub 0..3 channels, k 0..6 w-bins, 28
// active lanes). d/h loops are warp-uniform (i,j fixed per warp) -> zero
// divergence. Each (d,h) row of f is ONE 128B line; all 7 k-lanes of a c_sub
// coalesce into it -> 4 line-wavefronts per LDG. w-window loads predicated on
// per-lane width (1..3), so traffic = actual bytes only.

#define R_BINS 7
#define C_CH   64
#define DIMMAX 32
#define NTHREADS 256
#define WARPS_PB 8
#define TASKS_PER_PROP (16 * 49)    // ch-groups x (i,j) = 784 warp-tasks
#define BLOCKS_Y (TASKS_PER_PROP / WARPS_PB)   // 98

__global__ __launch_bounds__(NTHREADS) void crop_roi_kernel(
        const float* __restrict__ f,
        const float* __restrict__ props,
        float* __restrict__ out) {
    const int n    = blockIdx.x;
    const int tid  = threadIdx.x;
    const int lane = tid & 31;
    const int warp = tid >> 5;

    __shared__ int sS[3][R_BINS], sE[3][R_BINS];
    __shared__ int sB;

    // ---- bounds (21 threads), bitwise-identical to reference math ----
    if (tid < 3 * R_BINS) {
        const int ax = tid / R_BINS;
        const int bi = tid - ax * R_BINS;
        const float* p = props + (size_t)n * 8;
        if (tid == 0) sB = (int)p[0];
        float center = __ldg(p + 2 + ax);
        float side   = __ldg(p + 5 + ax);
        // *0.5f and *0.25f exact (powers of two) -> matches jnp arithmetic
        int c0 = (int)floorf((center - 0.5f * side) * 0.25f);
        int c1 = (int)ceilf ((center + 0.5f * side) * 0.25f);
        c0 = max(c0, 0);
        c1 = min(c1, DIMMAX);
        int L  = c1 - c0;
        int ss = c0 + (bi * L) / R_BINS;                     // floor div
        int ee = c0 + ((bi + 1) * L + R_BINS - 1) / R_BINS;  // ceil div
        ee = min(ee, ss + 6);                                // K cap (safety)
        sS[ax][bi] = ss;
        sE[ax][bi] = ee;
    }
    __syncthreads();

    // warp-task decomposition
    const int wt = blockIdx.y * WARPS_PB + warp;   // 0..783
    const int cg = wt / 49;                        // 0..15  (4-channel group)
    const int ij = wt - cg * 49;
    const int i  = ij / 7;
    const int j  = ij - i * 7;

    // lane roles: c_sub = lane>>3 (channel within group), k = lane&7 (w-bin)
    const int c_sub  = lane >> 3;
    const int k      = lane & 7;
    const bool active = (k < 7);
    const int kk     = active ? k : 0;             // clamp for safe smem read

    // warp-uniform d/h bounds
    const int sd = sS[0][i], ed = sE[0][i];
    const int sh = sS[1][j], eh = sE[1][j];
    // per-lane w-window
    const int w0 = sS[2][kk];
    const int ww = sE[2][kk] - w0;                 // width in [1,3]

    const int ch = cg * 4 + c_sub;
    const float* base = f + (((size_t)sB * C_CH + ch) << 15) + w0;

    float m = -3.402823466e+38f;                   // finfo(float32).min

    for (int d = sd; d < ed; d++) {
        const float* pd = base + (d << 10);
        for (int h = sh; h < eh; h++) {
            const float* p = pd + (h << 5);
            float v = p[0];                        // 4 lines/warp (k-lanes coalesce)
            if (ww > 1) v = fmaxf(v, p[1]);        // predicated: no traffic if width==1
            if (ww > 2) v = fmaxf(v, p[2]);
            m = fmaxf(m, v);
        }
    }

    if (active) {
        out[((size_t)n * C_CH + ch) * 343 + ij * 7 + k] = m;
    }
}

extern "C" void kernel_launch(void* const* d_in, const int* in_sizes, int n_in,
                              void* d_out, int out_size) {
    const float* f     = (const float*)d_in[0];
    const float* props = (const float*)d_in[2];
    float* out = (float*)d_out;

    int n_props = in_sizes[2] / 8;
    dim3 grid(n_props, BLOCKS_Y);
    crop_roi_kernel<<<grid, NTHREADS>>>(f, props, out);
}

// round 15
// speedup vs baseline: 1.3743x; 1.3743x over previous
#include <cuda_runtime.h>
#include <cuda_bf16.h>
#include <math.h>

// CropRoi: f (B=4, C=64, 32,32,32) f32; proposals (N,8) [b,score,cx,cy,cz,sx,sy,sz]
// out (N,C,7,7,7) f32. dims_max=32, R=7. L=c1-c0 in [2,13] => bin widths in [1,3].
//
// Block = (proposal n, (i,j) bin pair): d/h loop bounds uniform across the
// whole block. 4 warps x 16 channels: lane = c_sub*8 + k (c_sub: channel
// within 4-ch slot, k: w-bin, 28 active lanes). Each warp accumulates 4
// channel-slots (16 ch) via fixed-immediate-offset loads -> per (d,h) iter:
// 4 unconditional + 8 predicated LDGs batched (12-wide MLP), each LDG
// touching exactly 4 x 128B lines (k-lanes coalesce within a row-line).

#define R_BINS 7
#define C_CH   64
#define DIMMAX 32
#define NTHREADS 128
#define QS (4 * 32768)      // floats between channel-slots (4 channels)

__global__ __launch_bounds__(NTHREADS) void crop_roi_kernel(
        const float* __restrict__ f,
        const float* __restrict__ props,
        float* __restrict__ out) {
    const int n    = blockIdx.x;
    const int ij   = blockIdx.y;            // 0..48
    const int tid  = threadIdx.x;
    const int lane = tid & 31;
    const int warp = tid >> 5;

    __shared__ int sS[3][R_BINS], sE[3][R_BINS];
    __shared__ int sB;

    // ---- bounds (21 threads), bitwise-identical to reference math ----
    if (tid < 3 * R_BINS) {
        const int ax = tid / R_BINS;
        const int bi = tid - ax * R_BINS;
        const float* p = props + (size_t)n * 8;
        if (tid == 0) sB = (int)p[0];
        float center = __ldg(p + 2 + ax);
        float side   = __ldg(p + 5 + ax);
        // *0.5f and *0.25f exact (powers of two) -> matches jnp arithmetic
        int c0 = (int)floorf((center - 0.5f * side) * 0.25f);
        int c1 = (int)ceilf ((center + 0.5f * side) * 0.25f);
        c0 = max(c0, 0);
        c1 = min(c1, DIMMAX);
        int L  = c1 - c0;
        int ss = c0 + (bi * L) / R_BINS;                     // floor div
        int ee = c0 + ((bi + 1) * L + R_BINS - 1) / R_BINS;  // ceil div
        ee = min(ee, ss + 6);                                // K cap (safety)
        sS[ax][bi] = ss;
        sE[ax][bi] = ee;
    }
    __syncthreads();

    const int i = ij / 7;
    const int j = ij - i * 7;

    // block-uniform d/h bounds
    const int sd = sS[0][i], ed = sE[0][i];
    const int sh = sS[1][j], eh = sE[1][j];

    // lane roles
    const int  c_sub  = lane >> 3;          // 0..3
    const int  k      = lane & 7;           // 0..7 (7 inactive)
    const bool active = (k < 7);
    const int  kk     = active ? k : 0;
    const int  w0     = sS[2][kk];
    const int  ww     = sE[2][kk] - w0;     // width in [1,3]

    const int ch0 = warp * 16 + c_sub;      // first channel of this lane
    const float* base = f + (((size_t)sB * C_CH + ch0) << 15) + w0;

    const float NEG = -3.402823466e+38f;    // finfo(float32).min
    float m0 = NEG, m1 = NEG, m2 = NEG, m3 = NEG;

    for (int d = sd; d < ed; d++) {
        const float* pd = base + (d << 10);
        for (int h = sh; h < eh; h++) {
            const float* p = pd + (h << 5);
            // 4 channel-slots, fixed immediate offsets; k-lanes coalesce
            float a0 = p[0 * QS];
            float a1 = p[1 * QS];
            float a2 = p[2 * QS];
            float a3 = p[3 * QS];
            if (ww > 1) {                   // predicated: traffic only if real
                a0 = fmaxf(a0, p[1 + 0 * QS]);
                a1 = fmaxf(a1, p[1 + 1 * QS]);
                a2 = fmaxf(a2, p[1 + 2 * QS]);
                a3 = fmaxf(a3, p[1 + 3 * QS]);
            }
            if (ww > 2) {
                a0 = fmaxf(a0, p[2 + 0 * QS]);
                a1 = fmaxf(a1, p[2 + 1 * QS]);
                a2 = fmaxf(a2, p[2 + 2 * QS]);
                a3 = fmaxf(a3, p[2 + 3 * QS]);
            }
            m0 = fmaxf(m0, a0);
            m1 = fmaxf(m1, a1);
            m2 = fmaxf(m2, a2);
            m3 = fmaxf(m3, a3);
        }
    }

    if (active) {
        size_t o = ((size_t)n * C_CH + ch0) * 343 + ij * 7 + k;
        out[o]            = m0;
        out[o +  4 * 343] = m1;
        out[o +  8 * 343] = m2;
        out[o + 12 * 343] = m3;
    }
}

extern "C" void kernel_launch(void* const* d_in, const int* in_sizes, int n_in,
                              void* d_out, int out_size) {
    const float* f     = (const float*)d_in[0];
    const float* props = (const float*)d_in[2];
    float* out = (float*)d_out;

    int n_props = in_sizes[2] / 8;
    dim3 grid(n_props, 49);
    crop_roi_kernel<<<grid, NTHREADS>>>(f, props, out);
}